// round 8
// baseline (speedup 1.0000x reference)
#include <cuda_runtime.h>
#include <cuda_bf16.h>

// Problem constants (fixed shapes for CagnetSAGE)
#define NODES 100000
#define EDGES 1600000
#define D     128

// ---------------- static device scratch (no dynamic allocation allowed) ----
__device__ int   g_deg[NODES];
__device__ int   g_rowptr[NODES + 1];
__device__ int   g_cursor[NODES];
__device__ int   g_col[EDGES];
__device__ float g_inv_deg[NODES];
__device__ float g_agg[(size_t)NODES * D];   // 51.2 MB
__device__ float g_h1 [(size_t)NODES * D];   // 51.2 MB

// ---------------- CSR build ------------------------------------------------
__global__ void k_zero_deg(int n) {
    int i = blockIdx.x * blockDim.x + threadIdx.x;
    if (i < n) g_deg[i] = 0;
}

__global__ void k_count(const int* __restrict__ dst, int e) {
    int i = blockIdx.x * blockDim.x + threadIdx.x;
    if (i < e) atomicAdd(&g_deg[dst[i]], 1);
}

// Single-CTA 1024-thread exclusive scan over degrees -> rowptr / cursor / inv_deg
__global__ void k_scan(int n) {
    __shared__ int s_sum[1024];
    int t = threadIdx.x;
    int chunk = (n + 1023) / 1024;
    int beg = t * chunk;
    int end = min(beg + chunk, n);

    int s = 0;
    for (int i = beg; i < end; i++) s += g_deg[i];
    s_sum[t] = s;
    __syncthreads();

    // Hillis-Steele inclusive scan of per-thread sums
    for (int off = 1; off < 1024; off <<= 1) {
        int v = (t >= off) ? s_sum[t - off] : 0;
        __syncthreads();
        s_sum[t] += v;
        __syncthreads();
    }

    int run = (t == 0) ? 0 : s_sum[t - 1];
    for (int i = beg; i < end; i++) {
        int d = g_deg[i];
        g_rowptr[i]  = run;
        g_cursor[i]  = run;
        g_inv_deg[i] = 1.0f / (float)max(d, 1);
        run += d;
    }
    if (t == 1023) g_rowptr[n] = s_sum[1023];
}

__global__ void k_fill(const int* __restrict__ src, const int* __restrict__ dst, int e) {
    int i = blockIdx.x * blockDim.x + threadIdx.x;
    if (i < e) {
        int d = dst[i];
        int p = atomicAdd(&g_cursor[d], 1);
        g_col[p] = src[i];
    }
}

// ---------------- mean aggregation: one warp per node ----------------------
// out[node] = inv_deg[node] * sum_{s in neigh(node)} feat[s]
__global__ void k_agg(const float* __restrict__ feat, float* __restrict__ out, int n) {
    int warp = (blockIdx.x * blockDim.x + threadIdx.x) >> 5;
    if (warp >= n) return;
    int lane = threadIdx.x & 31;

    int beg = g_rowptr[warp];
    int end = g_rowptr[warp + 1];

    const float4* f4 = reinterpret_cast<const float4*>(feat);

    float4 a0 = make_float4(0.f, 0.f, 0.f, 0.f);
    float4 a1 = make_float4(0.f, 0.f, 0.f, 0.f);

    int e = beg;
    for (; e + 1 < end; e += 2) {
        int s0 = __ldg(&g_col[e]);
        int s1 = __ldg(&g_col[e + 1]);
        float4 v0 = f4[(size_t)s0 * 32 + lane];
        float4 v1 = f4[(size_t)s1 * 32 + lane];
        a0.x += v0.x; a0.y += v0.y; a0.z += v0.z; a0.w += v0.w;
        a1.x += v1.x; a1.y += v1.y; a1.z += v1.z; a1.w += v1.w;
    }
    if (e < end) {
        int s0 = __ldg(&g_col[e]);
        float4 v0 = f4[(size_t)s0 * 32 + lane];
        a0.x += v0.x; a0.y += v0.y; a0.z += v0.z; a0.w += v0.w;
    }

    float id = g_inv_deg[warp];
    float4 r;
    r.x = (a0.x + a1.x) * id;
    r.y = (a0.y + a1.y) * id;
    r.z = (a0.z + a1.z) * id;
    r.w = (a0.w + a1.w) * id;
    reinterpret_cast<float4*>(out)[(size_t)warp * 32 + lane] = r;
}

// ---------------- fused dual GEMM: C = relu?(A1@Wn^T + A2@Ws^T + bn + bs) ---
// A1,A2: [n,128] fp32. Wn,Ws: [128,128] row-major (out,in). C: [n,128].
// Treated as [n,256] @ [256,128]: full transposed weights resident in SMEM.
#define TM   64
#define APAD 260   // 64-row A tile row stride (pad for bank spread)
#define WPAD 132   // weight row stride (16B aligned, conflict-free float4 reads)

template<bool RELU>
__global__ void __launch_bounds__(256, 1)
k_gemm(const float* __restrict__ A1, const float* __restrict__ A2,
       const float* __restrict__ Wn, const float* __restrict__ Ws,
       const float* __restrict__ bn, const float* __restrict__ bs,
       float* __restrict__ C, int n) {
    extern __shared__ float sh[];
    float* Ash = sh;                         // TM x APAD (cols 0..255 used)
    float* Wsh = sh + TM * APAD;             // 256 x WPAD (Wsh[k][o])

    int tid  = threadIdx.x;
    int row0 = blockIdx.x * TM;

    // Weights transposed into SMEM: Wsh[k][o] = W[o][k]
    for (int idx = tid; idx < 128 * 128; idx += 256) {
        int o = idx >> 7, k = idx & 127;
        Wsh[k * WPAD + o]          = Wn[idx];
        Wsh[(k + 128) * WPAD + o]  = Ws[idx];
    }
    // A tile: row r, cols 0..127 = A1, 128..255 = A2
    for (int idx = tid; idx < TM * 256; idx += 256) {
        int r = idx >> 8, c = idx & 255;
        int row = row0 + r;
        float v = 0.f;
        if (row < n) v = (c < 128) ? A1[(size_t)row * 128 + c]
                                   : A2[(size_t)row * 128 + (c - 128)];
        Ash[r * APAD + c] = v;
    }
    __syncthreads();

    int tr = tid >> 4;   // 0..15  -> rows tr, tr+16, tr+32, tr+48
    int tc = tid & 15;   // 0..15  -> cols tc*8 .. tc*8+7

    float acc[4][8];
    #pragma unroll
    for (int i = 0; i < 4; i++)
        #pragma unroll
        for (int j = 0; j < 8; j++) acc[i][j] = 0.f;

    #pragma unroll 4
    for (int k = 0; k < 256; k++) {
        float a[4];
        a[0] = Ash[(tr)      * APAD + k];
        a[1] = Ash[(tr + 16) * APAD + k];
        a[2] = Ash[(tr + 32) * APAD + k];
        a[3] = Ash[(tr + 48) * APAD + k];
        float4 b0 = *reinterpret_cast<const float4*>(&Wsh[k * WPAD + tc * 8]);
        float4 b1 = *reinterpret_cast<const float4*>(&Wsh[k * WPAD + tc * 8 + 4]);
        #pragma unroll
        for (int i = 0; i < 4; i++) {
            acc[i][0] += a[i] * b0.x;
            acc[i][1] += a[i] * b0.y;
            acc[i][2] += a[i] * b0.z;
            acc[i][3] += a[i] * b0.w;
            acc[i][4] += a[i] * b1.x;
            acc[i][5] += a[i] * b1.y;
            acc[i][6] += a[i] * b1.z;
            acc[i][7] += a[i] * b1.w;
        }
    }

    float bsum[8];
    #pragma unroll
    for (int j = 0; j < 8; j++) bsum[j] = bn[tc * 8 + j] + bs[tc * 8 + j];

    #pragma unroll
    for (int i = 0; i < 4; i++) {
        int row = row0 + tr + i * 16;
        if (row < n) {
            float4 o0, o1;
            float v;
            v = acc[i][0] + bsum[0]; o0.x = RELU ? fmaxf(v, 0.f) : v;
            v = acc[i][1] + bsum[1]; o0.y = RELU ? fmaxf(v, 0.f) : v;
            v = acc[i][2] + bsum[2]; o0.z = RELU ? fmaxf(v, 0.f) : v;
            v = acc[i][3] + bsum[3]; o0.w = RELU ? fmaxf(v, 0.f) : v;
            v = acc[i][4] + bsum[4]; o1.x = RELU ? fmaxf(v, 0.f) : v;
            v = acc[i][5] + bsum[5]; o1.y = RELU ? fmaxf(v, 0.f) : v;
            v = acc[i][6] + bsum[6]; o1.z = RELU ? fmaxf(v, 0.f) : v;
            v = acc[i][7] + bsum[7]; o1.w = RELU ? fmaxf(v, 0.f) : v;
            float4* cp = reinterpret_cast<float4*>(&C[(size_t)row * 128 + tc * 8]);
            cp[0] = o0;
            cp[1] = o1;
        }
    }
}

// ---------------- launcher --------------------------------------------------
extern "C" void kernel_launch(void* const* d_in, const int* in_sizes, int n_in,
                              void* d_out, int out_size) {
    const float* x    = (const float*)d_in[0];
    const int*   edge = (const int*)  d_in[1];
    const float* Wn1  = (const float*)d_in[2];
    const float* bn1  = (const float*)d_in[3];
    const float* Ws1  = (const float*)d_in[4];
    const float* bs1  = (const float*)d_in[5];
    const float* Wn2  = (const float*)d_in[6];
    const float* bn2  = (const float*)d_in[7];
    const float* Ws2  = (const float*)d_in[8];
    const float* bs2  = (const float*)d_in[9];
    float* out = (float*)d_out;

    int n = in_sizes[0] / D;     // 100000
    int e = in_sizes[1] / 2;     // 1600000
    const int* src = edge;
    const int* dst = edge + e;

    float* agg_p; cudaGetSymbolAddress((void**)&agg_p, g_agg);
    float* h1_p;  cudaGetSymbolAddress((void**)&h1_p,  g_h1);

    const size_t smem = (size_t)(TM * APAD + 256 * WPAD) * sizeof(float); // ~197 KB
    cudaFuncSetAttribute(k_gemm<true>,  cudaFuncAttributeMaxDynamicSharedMemorySize, (int)smem);
    cudaFuncSetAttribute(k_gemm<false>, cudaFuncAttributeMaxDynamicSharedMemorySize, (int)smem);

    // 1) CSR build (rebuilt every call: deterministic-work requirement)
    k_zero_deg<<<(n + 255) / 256, 256>>>(n);
    k_count   <<<(e + 255) / 256, 256>>>(dst, e);
    k_scan    <<<1, 1024>>>(n);
    k_fill    <<<(e + 255) / 256, 256>>>(src, dst, e);

    int agg_blocks  = (n + 7) / 8;            // 8 warps (256 threads) per block
    int gemm_blocks = (n + TM - 1) / TM;

    // 2) layer 1
    k_agg<<<agg_blocks, 256>>>(x, agg_p, n);
    k_gemm<true><<<gemm_blocks, 256, smem>>>(agg_p, x, Wn1, Ws1, bn1, bs1, h1_p, n);

    // 3) layer 2
    k_agg<<<agg_blocks, 256>>>(h1_p, agg_p, n);
    k_gemm<false><<<gemm_blocks, 256, smem>>>(agg_p, h1_p, Wn2, Ws2, bn2, bs2, out, n);
}

// round 9
// speedup vs baseline: 1.0134x; 1.0134x over previous
#include <cuda_runtime.h>
#include <cuda_bf16.h>

// Problem constants (fixed shapes for CagnetSAGE)
#define NODES 100000
#define EDGES 1600000
#define D     128

// ---------------- static device scratch (no dynamic allocation allowed) ----
__device__ int   g_deg[NODES];
__device__ int   g_rowptr[NODES + 1];
__device__ int   g_cursor[NODES];
__device__ int   g_col[EDGES];
__device__ float g_inv_deg[NODES];
__device__ float g_agg[(size_t)NODES * D];   // 51.2 MB
__device__ float g_h1 [(size_t)NODES * D];   // 51.2 MB

// ---------------- CSR build ------------------------------------------------
__global__ void k_zero_deg(int n) {
    int i = blockIdx.x * blockDim.x + threadIdx.x;
    if (i < n) g_deg[i] = 0;
}

__global__ void k_count(const int* __restrict__ dst, int e) {
    int i = blockIdx.x * blockDim.x + threadIdx.x;
    if (i < e) atomicAdd(&g_deg[dst[i]], 1);
}

// Single-CTA 1024-thread exclusive scan over degrees -> rowptr / cursor / inv_deg
__global__ void k_scan(int n) {
    __shared__ int s_sum[1024];
    int t = threadIdx.x;
    int chunk = (n + 1023) / 1024;
    int beg = t * chunk;
    int end = min(beg + chunk, n);

    int s = 0;
    for (int i = beg; i < end; i++) s += g_deg[i];
    s_sum[t] = s;
    __syncthreads();

    // Hillis-Steele inclusive scan of per-thread sums
    for (int off = 1; off < 1024; off <<= 1) {
        int v = (t >= off) ? s_sum[t - off] : 0;
        __syncthreads();
        s_sum[t] += v;
        __syncthreads();
    }

    int run = (t == 0) ? 0 : s_sum[t - 1];
    for (int i = beg; i < end; i++) {
        int d = g_deg[i];
        g_rowptr[i]  = run;
        g_cursor[i]  = run;
        g_inv_deg[i] = 1.0f / (float)max(d, 1);
        run += d;
    }
    if (t == 1023) g_rowptr[n] = s_sum[1023];
}

__global__ void k_fill(const int* __restrict__ src, const int* __restrict__ dst, int e) {
    int i = blockIdx.x * blockDim.x + threadIdx.x;
    if (i < e) {
        int d = dst[i];
        int p = atomicAdd(&g_cursor[d], 1);
        g_col[p] = src[i];
    }
}

// ---------------- mean aggregation: one warp per node ----------------------
// out[node] = inv_deg[node] * sum_{s in neigh(node)} feat[s]
__global__ void k_agg(const float* __restrict__ feat, float* __restrict__ out, int n) {
    int warp = (blockIdx.x * blockDim.x + threadIdx.x) >> 5;
    if (warp >= n) return;
    int lane = threadIdx.x & 31;

    int beg = g_rowptr[warp];
    int end = g_rowptr[warp + 1];

    const float4* f4 = reinterpret_cast<const float4*>(feat);

    float4 a0 = make_float4(0.f, 0.f, 0.f, 0.f);
    float4 a1 = make_float4(0.f, 0.f, 0.f, 0.f);

    int e = beg;
    for (; e + 1 < end; e += 2) {
        int s0 = __ldg(&g_col[e]);
        int s1 = __ldg(&g_col[e + 1]);
        float4 v0 = f4[(size_t)s0 * 32 + lane];
        float4 v1 = f4[(size_t)s1 * 32 + lane];
        a0.x += v0.x; a0.y += v0.y; a0.z += v0.z; a0.w += v0.w;
        a1.x += v1.x; a1.y += v1.y; a1.z += v1.z; a1.w += v1.w;
    }
    if (e < end) {
        int s0 = __ldg(&g_col[e]);
        float4 v0 = f4[(size_t)s0 * 32 + lane];
        a0.x += v0.x; a0.y += v0.y; a0.z += v0.z; a0.w += v0.w;
    }

    float id = g_inv_deg[warp];
    float4 r;
    r.x = (a0.x + a1.x) * id;
    r.y = (a0.y + a1.y) * id;
    r.z = (a0.z + a1.z) * id;
    r.w = (a0.w + a1.w) * id;
    reinterpret_cast<float4*>(out)[(size_t)warp * 32 + lane] = r;
}

// ---------------- fused dual GEMM: C = relu?(A1@Wn^T + A2@Ws^T + bn + bs) ---
// A1,A2: [n,128] fp32. Wn,Ws: [128,128] row-major (out,in). C: [n,128].
// Treated as [n,256] @ [256,128]: full transposed weights resident in SMEM.
#define TM   64
#define APAD 260   // 64-row A tile row stride (pad for bank spread)
#define WPAD 132   // weight row stride (16B aligned, conflict-free float4 reads)

template<bool RELU>
__global__ void __launch_bounds__(256, 1)
k_gemm(const float* __restrict__ A1, const float* __restrict__ A2,
       const float* __restrict__ Wn, const float* __restrict__ Ws,
       const float* __restrict__ bn, const float* __restrict__ bs,
       float* __restrict__ C, int n) {
    extern __shared__ float sh[];
    float* Ash = sh;                         // TM x APAD (cols 0..255 used)
    float* Wsh = sh + TM * APAD;             // 256 x WPAD (Wsh[k][o])

    int tid  = threadIdx.x;
    int row0 = blockIdx.x * TM;

    // Weights transposed into SMEM: Wsh[k][o] = W[o][k]
    for (int idx = tid; idx < 128 * 128; idx += 256) {
        int o = idx >> 7, k = idx & 127;
        Wsh[k * WPAD + o]          = Wn[idx];
        Wsh[(k + 128) * WPAD + o]  = Ws[idx];
    }
    // A tile: row r, cols 0..127 = A1, 128..255 = A2
    for (int idx = tid; idx < TM * 256; idx += 256) {
        int r = idx >> 8, c = idx & 255;
        int row = row0 + r;
        float v = 0.f;
        if (row < n) v = (c < 128) ? A1[(size_t)row * 128 + c]
                                   : A2[(size_t)row * 128 + (c - 128)];
        Ash[r * APAD + c] = v;
    }
    __syncthreads();

    int tr = tid >> 4;   // 0..15  -> rows tr, tr+16, tr+32, tr+48
    int tc = tid & 15;   // 0..15  -> cols tc*8 .. tc*8+7

    float acc[4][8];
    #pragma unroll
    for (int i = 0; i < 4; i++)
        #pragma unroll
        for (int j = 0; j < 8; j++) acc[i][j] = 0.f;

    #pragma unroll 4
    for (int k = 0; k < 256; k++) {
        float a[4];
        a[0] = Ash[(tr)      * APAD + k];
        a[1] = Ash[(tr + 16) * APAD + k];
        a[2] = Ash[(tr + 32) * APAD + k];
        a[3] = Ash[(tr + 48) * APAD + k];
        float4 b0 = *reinterpret_cast<const float4*>(&Wsh[k * WPAD + tc * 8]);
        float4 b1 = *reinterpret_cast<const float4*>(&Wsh[k * WPAD + tc * 8 + 4]);
        #pragma unroll
        for (int i = 0; i < 4; i++) {
            acc[i][0] += a[i] * b0.x;
            acc[i][1] += a[i] * b0.y;
            acc[i][2] += a[i] * b0.z;
            acc[i][3] += a[i] * b0.w;
            acc[i][4] += a[i] * b1.x;
            acc[i][5] += a[i] * b1.y;
            acc[i][6] += a[i] * b1.z;
            acc[i][7] += a[i] * b1.w;
        }
    }

    float bsum[8];
    #pragma unroll
    for (int j = 0; j < 8; j++) bsum[j] = bn[tc * 8 + j] + bs[tc * 8 + j];

    #pragma unroll
    for (int i = 0; i < 4; i++) {
        int row = row0 + tr + i * 16;
        if (row < n) {
            float4 o0, o1;
            float v;
            v = acc[i][0] + bsum[0]; o0.x = RELU ? fmaxf(v, 0.f) : v;
            v = acc[i][1] + bsum[1]; o0.y = RELU ? fmaxf(v, 0.f) : v;
            v = acc[i][2] + bsum[2]; o0.z = RELU ? fmaxf(v, 0.f) : v;
            v = acc[i][3] + bsum[3]; o0.w = RELU ? fmaxf(v, 0.f) : v;
            v = acc[i][4] + bsum[4]; o1.x = RELU ? fmaxf(v, 0.f) : v;
            v = acc[i][5] + bsum[5]; o1.y = RELU ? fmaxf(v, 0.f) : v;
            v = acc[i][6] + bsum[6]; o1.z = RELU ? fmaxf(v, 0.f) : v;
            v = acc[i][7] + bsum[7]; o1.w = RELU ? fmaxf(v, 0.f) : v;
            float4* cp = reinterpret_cast<float4*>(&C[(size_t)row * 128 + tc * 8]);
            cp[0] = o0;
            cp[1] = o1;
        }
    }
}

// ---------------- launcher --------------------------------------------------
extern "C" void kernel_launch(void* const* d_in, const int* in_sizes, int n_in,
                              void* d_out, int out_size) {
    const float* x    = (const float*)d_in[0];
    const int*   edge = (const int*)  d_in[1];
    const float* Wn1  = (const float*)d_in[2];
    const float* bn1  = (const float*)d_in[3];
    const float* Ws1  = (const float*)d_in[4];
    const float* bs1  = (const float*)d_in[5];
    const float* Wn2  = (const float*)d_in[6];
    const float* bn2  = (const float*)d_in[7];
    const float* Ws2  = (const float*)d_in[8];
    const float* bs2  = (const float*)d_in[9];
    float* out = (float*)d_out;

    int n = in_sizes[0] / D;     // 100000
    int e = in_sizes[1] / 2;     // 1600000
    const int* src = edge;
    const int* dst = edge + e;

    float* agg_p; cudaGetSymbolAddress((void**)&agg_p, g_agg);
    float* h1_p;  cudaGetSymbolAddress((void**)&h1_p,  g_h1);

    const size_t smem = (size_t)(TM * APAD + 256 * WPAD) * sizeof(float); // ~197 KB
    cudaFuncSetAttribute(k_gemm<true>,  cudaFuncAttributeMaxDynamicSharedMemorySize, (int)smem);
    cudaFuncSetAttribute(k_gemm<false>, cudaFuncAttributeMaxDynamicSharedMemorySize, (int)smem);

    // 1) CSR build (rebuilt every call: deterministic-work requirement)
    k_zero_deg<<<(n + 255) / 256, 256>>>(n);
    k_count   <<<(e + 255) / 256, 256>>>(dst, e);
    k_scan    <<<1, 1024>>>(n);
    k_fill    <<<(e + 255) / 256, 256>>>(src, dst, e);

    int agg_blocks  = (n + 7) / 8;            // 8 warps (256 threads) per block
    int gemm_blocks = (n + TM - 1) / TM;

    // 2) layer 1
    k_agg<<<agg_blocks, 256>>>(x, agg_p, n);
    k_gemm<true><<<gemm_blocks, 256, smem>>>(agg_p, x, Wn1, Ws1, bn1, bs1, h1_p, n);

    // 3) layer 2
    k_agg<<<agg_blocks, 256>>>(h1_p, agg_p, n);
    k_gemm<false><<<gemm_blocks, 256, smem>>>(agg_p, h1_p, Wn2, Ws2, bn2, bs2, out, n);
}